// round 15
// baseline (speedup 1.0000x reference)
#include <cuda_runtime.h>
#include <cuda_fp16.h>
#include <cstdint>

#define NN     100000
#define F_IN   128
#define F_HID  128
#define F_OUT  64
#define H1     8
#define EDGES  1600000
#define C1     33408          // pipeline chunk bounds: multiples of 128 and 4
#define C2     66816

// ---------------- scratch (static device globals; no allocs allowed) ----------------
__device__ __half g_feat1h[NN * F_HID];  // layer1 features, fp16 (gather + mirror)
__device__ float  g_el1[NN * H1];
__device__ float  g_er1[NN * H1];
__device__ __half g_h1h[NN * F_HID];     // layer1 output (bias added, pre-relu), fp16
__device__ __half g_feat2h[NN * F_OUT];  // layer2 features, fp16
__device__ float  g_el2[NN];
__device__ float  g_er2[NN];
// CSR by dst   (g_deg starts zero at module load; scan re-zeroes it each call)
__device__ int g_deg[NN];
__device__ int g_off[NN + 1];
__device__ int g_rank[EDGES];            // edge's rank within its dst bucket (from hist)
__device__ int g_esrc[EDGES];

__device__ __forceinline__ float leaky(float v) { return v > 0.f ? v : 0.2f * v; }

// ---------------- CSR build ----------------
// hist: count degree AND record each edge's rank (atomicAdd return value); MLP=4 (proven)
__global__ void hist_kernel(const int* __restrict__ dst, int E) {
    int i = (blockIdx.x * blockDim.x + threadIdx.x) * 4;
    if (i + 4 <= E) {
        int4 d = *reinterpret_cast<const int4*>(dst + i);
        int4 r;
        r.x = atomicAdd(&g_deg[d.x], 1);
        r.y = atomicAdd(&g_deg[d.y], 1);
        r.z = atomicAdd(&g_deg[d.z], 1);
        r.w = atomicAdd(&g_deg[d.w], 1);
        *reinterpret_cast<int4*>(g_rank + i) = r;
    } else {
        for (; i < E; i++) g_rank[i] = atomicAdd(&g_deg[dst[i]], 1);
    }
}

// single-block scan; vectorized; resets g_deg for next call
__global__ void scan_kernel(int E) {
    __shared__ int partials[1024];
    const int CH = 100;                       // 1024*100 >= NN; 100 % 4 == 0
    int t = threadIdx.x;
    int base = t * CH;
    int lim = min(base + CH, NN);
    int sum = 0;
    int i = base;
    for (; i + 4 <= lim; i += 4) {
        int4 v = *reinterpret_cast<const int4*>(g_deg + i);
        sum += v.x + v.y + v.z + v.w;
    }
    for (; i < lim; i++) sum += g_deg[i];
    partials[t] = sum;
    __syncthreads();
    for (int ofs = 1; ofs < 1024; ofs <<= 1) {
        int v = (t >= ofs) ? partials[t - ofs] : 0;
        __syncthreads();
        partials[t] += v;
        __syncthreads();
    }
    int run = partials[t] - sum;
    i = base;
    for (; i + 4 <= lim; i += 4) {
        int4 d = *reinterpret_cast<const int4*>(g_deg + i);
        int4 o;
        o.x = run;
        o.y = run + d.x;
        o.z = o.y + d.y;
        o.w = o.z + d.z;
        *reinterpret_cast<int4*>(g_off + i) = o;
        *reinterpret_cast<int4*>(g_deg + i) = make_int4(0, 0, 0, 0);
        run = o.w + d.w;
    }
    for (; i < lim; i++) {
        int d = g_deg[i];
        g_off[i] = run; g_deg[i] = 0;
        run += d;
    }
    if (t == 0) g_off[NN] = E;
}

// place: esrc[off[d] + rank] = src  -- no atomics, MLP=8 (independent chains)
__global__ void place_kernel(const int* __restrict__ src, const int* __restrict__ dst, int E) {
    int i = (blockIdx.x * blockDim.x + threadIdx.x) * 8;
    if (i + 8 <= E) {
        int4 s0 = *reinterpret_cast<const int4*>(src + i);
        int4 s1 = *reinterpret_cast<const int4*>(src + i + 4);
        int4 d0 = *reinterpret_cast<const int4*>(dst + i);
        int4 d1 = *reinterpret_cast<const int4*>(dst + i + 4);
        int4 r0 = *reinterpret_cast<const int4*>(g_rank + i);
        int4 r1 = *reinterpret_cast<const int4*>(g_rank + i + 4);
        int o0 = __ldg(g_off + d0.x);
        int o1 = __ldg(g_off + d0.y);
        int o2 = __ldg(g_off + d0.z);
        int o3 = __ldg(g_off + d0.w);
        int o4 = __ldg(g_off + d1.x);
        int o5 = __ldg(g_off + d1.y);
        int o6 = __ldg(g_off + d1.z);
        int o7 = __ldg(g_off + d1.w);
        g_esrc[o0 + r0.x] = s0.x;
        g_esrc[o1 + r0.y] = s0.y;
        g_esrc[o2 + r0.z] = s0.z;
        g_esrc[o3 + r0.w] = s0.w;
        g_esrc[o4 + r1.x] = s1.x;
        g_esrc[o5 + r1.y] = s1.y;
        g_esrc[o6 + r1.z] = s1.z;
        g_esrc[o7 + r1.w] = s1.w;
    } else {
        for (; i < E; i++) g_esrc[__ldg(g_off + dst[i]) + g_rank[i]] = src[i];
    }
}

// ---------------- tensor-core fp16 GEMM + fused elr epilogue ----------------
__device__ __forceinline__ uint32_t smem_u32(const void* p) {
    return (uint32_t)__cvta_generic_to_shared(p);
}
__device__ __forceinline__ void ldm_x4(uint32_t& r0, uint32_t& r1, uint32_t& r2, uint32_t& r3,
                                       uint32_t addr) {
    asm volatile("ldmatrix.sync.aligned.m8n8.x4.shared.b16 {%0,%1,%2,%3}, [%4];"
                 : "=r"(r0), "=r"(r1), "=r"(r2), "=r"(r3) : "r"(addr));
}
__device__ __forceinline__ void ldm_x4_t(uint32_t& r0, uint32_t& r1, uint32_t& r2, uint32_t& r3,
                                         uint32_t addr) {
    asm volatile("ldmatrix.sync.aligned.m8n8.x4.trans.shared.b16 {%0,%1,%2,%3}, [%4];"
                 : "=r"(r0), "=r"(r1), "=r"(r2), "=r"(r3) : "r"(addr));
}
__device__ __forceinline__ void mma16816(float& d0, float& d1, float& d2, float& d3,
                                         uint32_t a0, uint32_t a1, uint32_t a2, uint32_t a3,
                                         uint32_t b0, uint32_t b1) {
    asm volatile("mma.sync.aligned.m16n8k16.row.col.f32.f16.f16.f32 "
                 "{%0,%1,%2,%3}, {%4,%5,%6,%7}, {%8,%9}, {%0,%1,%2,%3};"
                 : "+f"(d0), "+f"(d1), "+f"(d2), "+f"(d3)
                 : "r"(a0), "r"(a1), "r"(a2), "r"(a3), "r"(b0), "r"(b1));
}

template<int BN, bool RELU_IN, typename AT>
__global__ __launch_bounds__(256)
void hgemm_fused(const AT* __restrict__ A, const float* __restrict__ B,
                 __half* __restrict__ Ch, float* __restrict__ gel, float* __restrict__ ger,
                 const float* __restrict__ attn_l, const float* __restrict__ attn_r,
                 int M, int Kd, int rowStart) {
    constexpr int BM = 128, BK = 32;
    constexpr int APAD = 8, BPAD = 8;
    constexpr int WN = BN / 2;
    constexpr int NT = WN / 8;
    __shared__ __align__(16) __half As[2][BM][BK + APAD];
    __shared__ __align__(16) __half Bs[2][BK][BN + BPAD];

    const int tid = threadIdx.x;
    const int wid = tid >> 5, lane = tid & 31;
    const int wm = wid & 3, wn = wid >> 2;
    const int rowBase = rowStart + blockIdx.x * BM;

    float acc[2][NT][4];
#pragma unroll
    for (int i = 0; i < 2; i++)
#pragma unroll
        for (int j = 0; j < NT; j++)
#pragma unroll
            for (int k = 0; k < 4; k++) acc[i][j][k] = 0.f;

    auto loadA = [&](int buf, int k0) {
#pragma unroll
        for (int it = 0; it < 2; it++) {
            int slot = tid + it * 256;
            int r = slot >> 2;
            int c8 = (slot & 3) * 8;
            int grow = rowBase + r;
            if constexpr (sizeof(AT) == 2) {
                uint4 u = make_uint4(0, 0, 0, 0);
                if (grow < M)
                    u = *reinterpret_cast<const uint4*>(A + (size_t)grow * Kd + k0 + c8);
                if (RELU_IN) {
                    half2 z = __float2half2_rn(0.f);
                    half2* hp = reinterpret_cast<half2*>(&u);
                    hp[0] = __hmax2(hp[0], z); hp[1] = __hmax2(hp[1], z);
                    hp[2] = __hmax2(hp[2], z); hp[3] = __hmax2(hp[3], z);
                }
                *reinterpret_cast<uint4*>(&As[buf][r][c8]) = u;
            } else {
                float4 v0 = make_float4(0.f, 0.f, 0.f, 0.f), v1 = v0;
                if (grow < M) {
                    const float* p = reinterpret_cast<const float*>(A) + (size_t)grow * Kd + k0 + c8;
                    v0 = *reinterpret_cast<const float4*>(p);
                    v1 = *reinterpret_cast<const float4*>(p + 4);
                }
                if (RELU_IN) {
                    v0.x = fmaxf(v0.x, 0.f); v0.y = fmaxf(v0.y, 0.f);
                    v0.z = fmaxf(v0.z, 0.f); v0.w = fmaxf(v0.w, 0.f);
                    v1.x = fmaxf(v1.x, 0.f); v1.y = fmaxf(v1.y, 0.f);
                    v1.z = fmaxf(v1.z, 0.f); v1.w = fmaxf(v1.w, 0.f);
                }
                half2 h0 = __floats2half2_rn(v0.x, v0.y);
                half2 h1 = __floats2half2_rn(v0.z, v0.w);
                half2 h2 = __floats2half2_rn(v1.x, v1.y);
                half2 h3 = __floats2half2_rn(v1.z, v1.w);
                uint4 u;
                u.x = *reinterpret_cast<unsigned*>(&h0);
                u.y = *reinterpret_cast<unsigned*>(&h1);
                u.z = *reinterpret_cast<unsigned*>(&h2);
                u.w = *reinterpret_cast<unsigned*>(&h3);
                *reinterpret_cast<uint4*>(&As[buf][r][c8]) = u;
            }
        }
    };
    auto loadB = [&](int buf, int k0) {
        constexpr int CG = BN / 8;
        constexpr int SLOTS = BK * CG;
        constexpr int ITERS = (SLOTS + 255) / 256;
#pragma unroll
        for (int it = 0; it < ITERS; it++) {
            int slot = tid + it * 256;
            if (SLOTS < 256 && slot >= SLOTS) break;
            int r = slot / CG;
            int c8 = (slot % CG) * 8;
            const float* p = B + (size_t)(k0 + r) * BN + c8;
            float4 v0 = *reinterpret_cast<const float4*>(p);
            float4 v1 = *reinterpret_cast<const float4*>(p + 4);
            half2 h0 = __floats2half2_rn(v0.x, v0.y);
            half2 h1 = __floats2half2_rn(v0.z, v0.w);
            half2 h2 = __floats2half2_rn(v1.x, v1.y);
            half2 h3 = __floats2half2_rn(v1.z, v1.w);
            uint4 u;
            u.x = *reinterpret_cast<unsigned*>(&h0);
            u.y = *reinterpret_cast<unsigned*>(&h1);
            u.z = *reinterpret_cast<unsigned*>(&h2);
            u.w = *reinterpret_cast<unsigned*>(&h3);
            *reinterpret_cast<uint4*>(&Bs[buf][r][c8]) = u;
        }
    };

    loadA(0, 0); loadB(0, 0);
    __syncthreads();
    const int KT = Kd / BK;
    for (int kt = 0; kt < KT; kt++) {
        int buf = kt & 1;
        if (kt + 1 < KT) { loadA(buf ^ 1, (kt + 1) * BK); loadB(buf ^ 1, (kt + 1) * BK); }
#pragma unroll
        for (int kc = 0; kc < 2; kc++) {
            int k16 = kc * 16;
            uint32_t af[2][4];
#pragma unroll
            for (int mt = 0; mt < 2; mt++) {
                uint32_t addr = smem_u32(&As[buf][wm * 32 + mt * 16 + (lane & 15)][k16 + (lane >> 4) * 8]);
                ldm_x4(af[mt][0], af[mt][1], af[mt][2], af[mt][3], addr);
            }
            uint32_t bf[NT][2];
#pragma unroll
            for (int nt2 = 0; nt2 < NT / 2; nt2++) {
                uint32_t addr = smem_u32(&Bs[buf][k16 + (lane & 15)][wn * WN + nt2 * 16 + (lane >> 4) * 8]);
                uint32_t r0, r1, r2, r3;
                ldm_x4_t(r0, r1, r2, r3, addr);
                bf[nt2 * 2][0] = r0; bf[nt2 * 2][1] = r1;
                bf[nt2 * 2 + 1][0] = r2; bf[nt2 * 2 + 1][1] = r3;
            }
#pragma unroll
            for (int mt = 0; mt < 2; mt++)
#pragma unroll
                for (int nt = 0; nt < NT; nt++)
                    mma16816(acc[mt][nt][0], acc[mt][nt][1], acc[mt][nt][2], acc[mt][nt][3],
                             af[mt][0], af[mt][1], af[mt][2], af[mt][3],
                             bf[nt][0], bf[nt][1]);
        }
        __syncthreads();
    }

    const int gid = lane >> 2, qid = lane & 3;

    // ---- fp16 mirror ----
#pragma unroll
    for (int mt = 0; mt < 2; mt++) {
        int r0 = rowBase + wm * 32 + mt * 16 + gid;
#pragma unroll
        for (int nt = 0; nt < NT; nt++) {
            int c = wn * WN + nt * 8 + qid * 2;
            if (r0 < M) {
                half2 hv = __floats2half2_rn(acc[mt][nt][0], acc[mt][nt][1]);
                *reinterpret_cast<unsigned*>(Ch + (size_t)r0 * BN + c) =
                    *reinterpret_cast<unsigned*>(&hv);
            }
            if (r0 + 8 < M) {
                half2 hv = __floats2half2_rn(acc[mt][nt][2], acc[mt][nt][3]);
                *reinterpret_cast<unsigned*>(Ch + (size_t)(r0 + 8) * BN + c) =
                    *reinterpret_cast<unsigned*>(&hv);
            }
        }
    }

    // ---- fused elr ----
    if constexpr (BN == 128) {
        float wl[16], wr[16];
#pragma unroll
        for (int nt = 0; nt < 8; nt++) {
            int c = wn * 64 + nt * 8 + qid * 2;
            wl[nt * 2 + 0] = __ldg(attn_l + c);
            wl[nt * 2 + 1] = __ldg(attn_l + c + 1);
            wr[nt * 2 + 0] = __ldg(attn_r + c);
            wr[nt * 2 + 1] = __ldg(attn_r + c + 1);
        }
#pragma unroll
        for (int mt = 0; mt < 2; mt++)
#pragma unroll
            for (int hf = 0; hf < 2; hf++) {
                int r = rowBase + wm * 32 + mt * 16 + hf * 8 + gid;
                float sel[4], ser[4];
#pragma unroll
                for (int hl = 0; hl < 4; hl++) {
                    int n0 = hl * 2, n1 = hl * 2 + 1;
                    sel[hl] = acc[mt][n0][hf * 2] * wl[n0 * 2] + acc[mt][n0][hf * 2 + 1] * wl[n0 * 2 + 1]
                            + acc[mt][n1][hf * 2] * wl[n1 * 2] + acc[mt][n1][hf * 2 + 1] * wl[n1 * 2 + 1];
                    ser[hl] = acc[mt][n0][hf * 2] * wr[n0 * 2] + acc[mt][n0][hf * 2 + 1] * wr[n0 * 2 + 1]
                            + acc[mt][n1][hf * 2] * wr[n1 * 2] + acc[mt][n1][hf * 2 + 1] * wr[n1 * 2 + 1];
                }
#pragma unroll
                for (int hl = 0; hl < 4; hl++) {
                    sel[hl] += __shfl_xor_sync(0xffffffffu, sel[hl], 1);
                    sel[hl] += __shfl_xor_sync(0xffffffffu, sel[hl], 2);
                    ser[hl] += __shfl_xor_sync(0xffffffffu, ser[hl], 1);
                    ser[hl] += __shfl_xor_sync(0xffffffffu, ser[hl], 2);
                }
                if (r < M) {
#pragma unroll
                    for (int hl = 0; hl < 4; hl++)
                        if (hl == qid) {
                            gel[(size_t)r * H1 + wn * 4 + hl] = sel[hl];
                            ger[(size_t)r * H1 + wn * 4 + hl] = ser[hl];
                        }
                }
            }
    } else {
        __shared__ float sEl[2][BM], sEr[2][BM];
        float wl[8], wr[8];
#pragma unroll
        for (int nt = 0; nt < 4; nt++) {
            int c = wn * 32 + nt * 8 + qid * 2;
            wl[nt * 2 + 0] = __ldg(attn_l + c);
            wl[nt * 2 + 1] = __ldg(attn_l + c + 1);
            wr[nt * 2 + 0] = __ldg(attn_r + c);
            wr[nt * 2 + 1] = __ldg(attn_r + c + 1);
        }
#pragma unroll
        for (int mt = 0; mt < 2; mt++)
#pragma unroll
            for (int hf = 0; hf < 2; hf++) {
                int lr = wm * 32 + mt * 16 + hf * 8 + gid;
                float sel = 0.f, ser = 0.f;
#pragma unroll
                for (int nt = 0; nt < 4; nt++) {
                    sel += acc[mt][nt][hf * 2] * wl[nt * 2] + acc[mt][nt][hf * 2 + 1] * wl[nt * 2 + 1];
                    ser += acc[mt][nt][hf * 2] * wr[nt * 2] + acc[mt][nt][hf * 2 + 1] * wr[nt * 2 + 1];
                }
                sel += __shfl_xor_sync(0xffffffffu, sel, 1);
                sel += __shfl_xor_sync(0xffffffffu, sel, 2);
                ser += __shfl_xor_sync(0xffffffffu, ser, 1);
                ser += __shfl_xor_sync(0xffffffffu, ser, 2);
                if (qid == 0) { sEl[wn][lr] = sel; sEr[wn][lr] = ser; }
            }
        __syncthreads();
        if (tid < BM) {
            int r = rowBase + tid;
            if (r < M) {
                gel[r] = sEl[0][tid] + sEl[1][tid];
                ger[r] = sEr[0][tid] + sEr[1][tid];
            }
        }
    }
}

// ---------------- layer1 agg: TWO warps per dst node, node-range variant ----------------
__global__ __launch_bounds__(256)
void agg1_kernel(const float* __restrict__ bias1, int nodeBase) {
    __shared__ float sAcc[4][32][5];
    int wid = threadIdx.x >> 5, lane = threadIdx.x & 31;
    int slot = wid >> 1, half = wid & 1;
    int w = nodeBase + blockIdx.x * 4 + slot;
    int h = lane >> 2;

    int beg = g_off[w], end = g_off[w + 1];
    int mid = (beg + end) >> 1;
    int b = half ? mid : beg;
    int e = half ? end : mid;
    float er_h = __ldg(g_er1 + (size_t)w * H1 + h);

    float acc0 = 0.f, acc1 = 0.f, acc2 = 0.f, acc3 = 0.f, ssum = 0.f;

    int i = b;
    for (; i + 4 <= e; i += 4) {
        int s0 = __ldg(g_esrc + i + 0);
        int s1 = __ldg(g_esrc + i + 1);
        int s2 = __ldg(g_esrc + i + 2);
        int s3 = __ldg(g_esrc + i + 3);
        float el0 = __ldg(g_el1 + (size_t)s0 * H1 + h);
        float el1 = __ldg(g_el1 + (size_t)s1 * H1 + h);
        float el2 = __ldg(g_el1 + (size_t)s2 * H1 + h);
        float el3 = __ldg(g_el1 + (size_t)s3 * H1 + h);
        uint2 u0 = *reinterpret_cast<const uint2*>(g_feat1h + (size_t)s0 * F_HID + lane * 4);
        uint2 u1 = *reinterpret_cast<const uint2*>(g_feat1h + (size_t)s1 * F_HID + lane * 4);
        uint2 u2 = *reinterpret_cast<const uint2*>(g_feat1h + (size_t)s2 * F_HID + lane * 4);
        uint2 u3 = *reinterpret_cast<const uint2*>(g_feat1h + (size_t)s3 * F_HID + lane * 4);
        float p0 = __expf(leaky(el0 + er_h));
        float p1 = __expf(leaky(el1 + er_h));
        float p2 = __expf(leaky(el2 + er_h));
        float p3 = __expf(leaky(el3 + er_h));
        {
            float2 a = __half22float2(*reinterpret_cast<half2*>(&u0.x));
            float2 c = __half22float2(*reinterpret_cast<half2*>(&u0.y));
            acc0 = fmaf(p0, a.x, acc0); acc1 = fmaf(p0, a.y, acc1);
            acc2 = fmaf(p0, c.x, acc2); acc3 = fmaf(p0, c.y, acc3);
        }
        {
            float2 a = __half22float2(*reinterpret_cast<half2*>(&u1.x));
            float2 c = __half22float2(*reinterpret_cast<half2*>(&u1.y));
            acc0 = fmaf(p1, a.x, acc0); acc1 = fmaf(p1, a.y, acc1);
            acc2 = fmaf(p1, c.x, acc2); acc3 = fmaf(p1, c.y, acc3);
        }
        {
            float2 a = __half22float2(*reinterpret_cast<half2*>(&u2.x));
            float2 c = __half22float2(*reinterpret_cast<half2*>(&u2.y));
            acc0 = fmaf(p2, a.x, acc0); acc1 = fmaf(p2, a.y, acc1);
            acc2 = fmaf(p2, c.x, acc2); acc3 = fmaf(p2, c.y, acc3);
        }
        {
            float2 a = __half22float2(*reinterpret_cast<half2*>(&u3.x));
            float2 c = __half22float2(*reinterpret_cast<half2*>(&u3.y));
            acc0 = fmaf(p3, a.x, acc0); acc1 = fmaf(p3, a.y, acc1);
            acc2 = fmaf(p3, c.x, acc2); acc3 = fmaf(p3, c.y, acc3);
        }
        ssum += (p0 + p1) + (p2 + p3);
    }
    for (; i < e; i++) {
        int s = __ldg(g_esrc + i);
        float el = __ldg(g_el1 + (size_t)s * H1 + h);
        uint2 u = *reinterpret_cast<const uint2*>(g_feat1h + (size_t)s * F_HID + lane * 4);
        float p = __expf(leaky(el + er_h));
        float2 a = __half22float2(*reinterpret_cast<half2*>(&u.x));
        float2 c = __half22float2(*reinterpret_cast<half2*>(&u.y));
        acc0 = fmaf(p, a.x, acc0); acc1 = fmaf(p, a.y, acc1);
        acc2 = fmaf(p, c.x, acc2); acc3 = fmaf(p, c.y, acc3);
        ssum += p;
    }

    if (half) {
        sAcc[slot][lane][0] = acc0;
        sAcc[slot][lane][1] = acc1;
        sAcc[slot][lane][2] = acc2;
        sAcc[slot][lane][3] = acc3;
        sAcc[slot][lane][4] = ssum;
    }
    __syncthreads();
    if (!half) {
        acc0 += sAcc[slot][lane][0];
        acc1 += sAcc[slot][lane][1];
        acc2 += sAcc[slot][lane][2];
        acc3 += sAcc[slot][lane][3];
        ssum += sAcc[slot][lane][4];
        float inv = 1.f / fmaxf(ssum, 1e-9f);
        float4 bb = *reinterpret_cast<const float4*>(bias1 + lane * 4);
        half2 o0 = __floats2half2_rn(acc0 * inv + bb.x, acc1 * inv + bb.y);
        half2 o1 = __floats2half2_rn(acc2 * inv + bb.z, acc3 * inv + bb.w);
        uint2 ou;
        ou.x = *reinterpret_cast<unsigned*>(&o0);
        ou.y = *reinterpret_cast<unsigned*>(&o1);
        *reinterpret_cast<uint2*>(g_h1h + (size_t)w * F_HID + lane * 4) = ou;
    }
}

// ---------------- layer2 agg: TWO warps per dst node ----------------
__global__ __launch_bounds__(256)
void agg2_kernel(const float* __restrict__ bias2, float* __restrict__ out) {
    __shared__ float sAcc[4][32][3];
    int wid = threadIdx.x >> 5, lane = threadIdx.x & 31;
    int slot = wid >> 1, half = wid & 1;
    int w = blockIdx.x * 4 + slot;

    int beg = g_off[w], end = g_off[w + 1];
    int mid = (beg + end) >> 1;
    int b = half ? mid : beg;
    int e = half ? end : mid;
    float er = __ldg(g_er2 + w);

    float acc0 = 0.f, acc1 = 0.f, ssum = 0.f;

    int i = b;
    for (; i + 4 <= e; i += 4) {
        int s0 = __ldg(g_esrc + i + 0);
        int s1 = __ldg(g_esrc + i + 1);
        int s2 = __ldg(g_esrc + i + 2);
        int s3 = __ldg(g_esrc + i + 3);
        float el0 = __ldg(g_el2 + s0);
        float el1 = __ldg(g_el2 + s1);
        float el2 = __ldg(g_el2 + s2);
        float el3 = __ldg(g_el2 + s3);
        unsigned u0 = *reinterpret_cast<const unsigned*>(g_feat2h + (size_t)s0 * F_OUT + lane * 2);
        unsigned u1 = *reinterpret_cast<const unsigned*>(g_feat2h + (size_t)s1 * F_OUT + lane * 2);
        unsigned u2 = *reinterpret_cast<const unsigned*>(g_feat2h + (size_t)s2 * F_OUT + lane * 2);
        unsigned u3 = *reinterpret_cast<const unsigned*>(g_feat2h + (size_t)s3 * F_OUT + lane * 2);
        float p0 = __expf(leaky(el0 + er));
        float p1 = __expf(leaky(el1 + er));
        float p2 = __expf(leaky(el2 + er));
        float p3 = __expf(leaky(el3 + er));
        float2 f0 = __half22float2(*reinterpret_cast<half2*>(&u0));
        float2 f1 = __half22float2(*reinterpret_cast<half2*>(&u1));
        float2 f2 = __half22float2(*reinterpret_cast<half2*>(&u2));
        float2 f3 = __half22float2(*reinterpret_cast<half2*>(&u3));
        acc0 = fmaf(p0, f0.x, acc0); acc1 = fmaf(p0, f0.y, acc1);
        acc0 = fmaf(p1, f1.x, acc0); acc1 = fmaf(p1, f1.y, acc1);
        acc0 = fmaf(p2, f2.x, acc0); acc1 = fmaf(p2, f2.y, acc1);
        acc0 = fmaf(p3, f3.x, acc0); acc1 = fmaf(p3, f3.y, acc1);
        ssum += (p0 + p1) + (p2 + p3);
    }
    for (; i < e; i++) {
        int s = __ldg(g_esrc + i);
        float el = __ldg(g_el2 + s);
        unsigned u = *reinterpret_cast<const unsigned*>(g_feat2h + (size_t)s * F_OUT + lane * 2);
        float p = __expf(leaky(el + er));
        float2 f = __half22float2(*reinterpret_cast<half2*>(&u));
        acc0 = fmaf(p, f.x, acc0); acc1 = fmaf(p, f.y, acc1);
        ssum += p;
    }

    if (half) {
        sAcc[slot][lane][0] = acc0;
        sAcc[slot][lane][1] = acc1;
        sAcc[slot][lane][2] = ssum;
    }
    __syncthreads();
    if (!half) {
        acc0 += sAcc[slot][lane][0];
        acc1 += sAcc[slot][lane][1];
        ssum += sAcc[slot][lane][2];
        float inv = 1.f / fmaxf(ssum, 1e-9f);
        float2 bb = *reinterpret_cast<const float2*>(bias2 + lane * 2);
        float2 o = make_float2(acc0 * inv + bb.x, acc1 * inv + bb.y);
        *reinterpret_cast<float2*>(out + (size_t)w * F_OUT + lane * 2) = o;
    }
}

// ---------------- launch ----------------
extern "C" void kernel_launch(void* const* d_in, const int* in_sizes, int n_in,
                              void* d_out, int out_size) {
    const float* x   = (const float*)d_in[0];
    const int*   src = (const int*)  d_in[1];
    const int*   dst = (const int*)  d_in[2];
    const float* W1  = (const float*)d_in[3];
    const float* al1 = (const float*)d_in[4];
    const float* ar1 = (const float*)d_in[5];
    const float* b1  = (const float*)d_in[6];
    const float* W2  = (const float*)d_in[7];
    const float* al2 = (const float*)d_in[8];
    const float* ar2 = (const float*)d_in[9];
    const float* b2  = (const float*)d_in[10];
    float* out = (float*)d_out;
    const int E = in_sizes[1];
    const int M = NN;

    __half *feat1h, *h1h, *feat2h;
    float *el1, *er1, *el2, *er2;
    cudaGetSymbolAddress((void**)&feat1h, g_feat1h);
    cudaGetSymbolAddress((void**)&h1h,    g_h1h);
    cudaGetSymbolAddress((void**)&feat2h, g_feat2h);
    cudaGetSymbolAddress((void**)&el1, g_el1);
    cudaGetSymbolAddress((void**)&er1, g_er1);
    cudaGetSymbolAddress((void**)&el2, g_el2);
    cudaGetSymbolAddress((void**)&er2, g_er2);

    static cudaStream_t s_side = nullptr;
    static cudaEvent_t  s_fork = nullptr, s_join = nullptr;
    static cudaEvent_t  s_evA1 = nullptr, s_evA2 = nullptr, s_evG = nullptr;
    if (!s_side) {
        cudaStreamCreateWithFlags(&s_side, cudaStreamNonBlocking);
        cudaEventCreateWithFlags(&s_fork, cudaEventDisableTiming);
        cudaEventCreateWithFlags(&s_join, cudaEventDisableTiming);
        cudaEventCreateWithFlags(&s_evA1, cudaEventDisableTiming);
        cudaEventCreateWithFlags(&s_evA2, cudaEventDisableTiming);
        cudaEventCreateWithFlags(&s_evG,  cudaEventDisableTiming);
    }

    // fork side stream
    cudaEventRecord(s_fork, 0);
    cudaStreamWaitEvent(s_side, s_fork, 0);

    // main: layer-1 GEMM
    hgemm_fused<F_HID, false, float><<<(M + 127) / 128, 256>>>(
        x, W1, feat1h, el1, er1, al1, ar1, M, F_IN, 0);

    // side: CSR build
    hist_kernel<<<(E / 4 + 255) / 256, 256, 0, s_side>>>(dst, E);
    scan_kernel<<<1, 1024, 0, s_side>>>(E);
    place_kernel<<<(E / 8 + 255) / 256, 256, 0, s_side>>>(src, dst, E);
    cudaEventRecord(s_join, s_side);

    // 3-chunk agg1 / gemm2 pipeline
    cudaStreamWaitEvent(0, s_join, 0);
    agg1_kernel<<<C1 / 4, 256>>>(b1, 0);
    cudaEventRecord(s_evA1, 0);

    cudaStreamWaitEvent(s_side, s_evA1, 0);
    hgemm_fused<F_OUT, true, __half><<<C1 / 128, 256, 0, s_side>>>(
        h1h, W2, feat2h, el2, er2, al2, ar2, M, F_HID, 0);

    agg1_kernel<<<(C2 - C1) / 4, 256>>>(b1, C1);
    cudaEventRecord(s_evA2, 0);

    cudaStreamWaitEvent(s_side, s_evA2, 0);
    hgemm_fused<F_OUT, true, __half><<<(C2 - C1) / 128, 256, 0, s_side>>>(
        h1h, W2, feat2h, el2, er2, al2, ar2, M, F_HID, C1);
    cudaEventRecord(s_evG, s_side);

    agg1_kernel<<<(NN - C2) / 4, 256>>>(b1, C2);
    hgemm_fused<F_OUT, true, __half><<<(M - C2 + 127) / 128, 256>>>(
        h1h, W2, feat2h, el2, er2, al2, ar2, M, F_HID, C2);

    // agg2 needs all gemm2 chunks
    cudaStreamWaitEvent(0, s_evG, 0);
    agg2_kernel<<<NN / 4, 256>>>(b2, out);
}

// round 16
// speedup vs baseline: 1.0220x; 1.0220x over previous
#include <cuda_runtime.h>
#include <cuda_fp16.h>
#include <cstdint>

#define NN     100000
#define F_IN   128
#define F_HID  128
#define F_OUT  64
#define H1     8
#define EDGES  1600000
#define NSPLIT 50048          // pipeline split: multiple of 128 (gemm rows) and 4 (agg nodes)

// ---------------- scratch (static device globals; no allocs allowed) ----------------
__device__ __half g_feat1h[NN * F_HID];  // layer1 features, fp16 (gather + mirror)
__device__ float  g_el1[NN * H1];
__device__ float  g_er1[NN * H1];
__device__ __half g_h1h[NN * F_HID];     // layer1 output (bias added, pre-relu), fp16
__device__ __half g_feat2h[NN * F_OUT];  // layer2 features, fp16
__device__ float  g_el2[NN];
__device__ float  g_er2[NN];
// CSR by dst   (g_deg starts zero at module load; scan re-zeroes it each call)
__device__ int g_deg[NN];
__device__ int g_off[NN + 1];
__device__ int g_rank[EDGES];            // edge's rank within its dst bucket (from hist)
__device__ int g_esrc[EDGES];

__device__ __forceinline__ float leaky(float v) { return v > 0.f ? v : 0.2f * v; }

// ---------------- CSR build ----------------
// hist: count degree AND record each edge's rank (atomicAdd return value); MLP=4 (proven)
__global__ void hist_kernel(const int* __restrict__ dst, int E) {
    int i = (blockIdx.x * blockDim.x + threadIdx.x) * 4;
    if (i + 4 <= E) {
        int4 d = *reinterpret_cast<const int4*>(dst + i);
        int4 r;
        r.x = atomicAdd(&g_deg[d.x], 1);
        r.y = atomicAdd(&g_deg[d.y], 1);
        r.z = atomicAdd(&g_deg[d.z], 1);
        r.w = atomicAdd(&g_deg[d.w], 1);
        *reinterpret_cast<int4*>(g_rank + i) = r;
    } else {
        for (; i < E; i++) g_rank[i] = atomicAdd(&g_deg[dst[i]], 1);
    }
}

// single-block scan; warp-shuffle scan (2 barriers); resets g_deg for next call
__global__ void scan_kernel(int E) {
    __shared__ int warpsum[32];
    const int CH = 100;                       // 1024*100 >= NN; 100 % 4 == 0
    int t = threadIdx.x;
    int lane = t & 31, wrp = t >> 5;
    int base = t * CH;
    int lim = min(base + CH, NN);
    int sum = 0;
    int i = base;
    for (; i + 4 <= lim; i += 4) {
        int4 v = *reinterpret_cast<const int4*>(g_deg + i);
        sum += v.x + v.y + v.z + v.w;
    }
    for (; i < lim; i++) sum += g_deg[i];

    // inclusive scan of per-thread sums: warp shuffle + single smem combine
    int v = sum;
#pragma unroll
    for (int ofs = 1; ofs < 32; ofs <<= 1) {
        int n = __shfl_up_sync(0xffffffffu, v, ofs);
        if (lane >= ofs) v += n;
    }
    if (lane == 31) warpsum[wrp] = v;
    __syncthreads();
    if (wrp == 0) {
        int w = warpsum[lane];
#pragma unroll
        for (int ofs = 1; ofs < 32; ofs <<= 1) {
            int n = __shfl_up_sync(0xffffffffu, w, ofs);
            if (lane >= ofs) w += n;
        }
        warpsum[lane] = w;
    }
    __syncthreads();
    int incl = v + (wrp > 0 ? warpsum[wrp - 1] : 0);
    int run = incl - sum;                    // exclusive prefix for this chunk

    i = base;
    for (; i + 4 <= lim; i += 4) {
        int4 d = *reinterpret_cast<const int4*>(g_deg + i);
        int4 o;
        o.x = run;
        o.y = run + d.x;
        o.z = o.y + d.y;
        o.w = o.z + d.z;
        *reinterpret_cast<int4*>(g_off + i) = o;
        *reinterpret_cast<int4*>(g_deg + i) = make_int4(0, 0, 0, 0);
        run = o.w + d.w;
    }
    for (; i < lim; i++) {
        int d = g_deg[i];
        g_off[i] = run; g_deg[i] = 0;
        run += d;
    }
    if (t == 0) g_off[NN] = E;
}

// place: esrc[off[d] + rank] = src  -- no atomics, MLP=4 (proven optimum)
__global__ void place_kernel(const int* __restrict__ src, const int* __restrict__ dst, int E) {
    int i = (blockIdx.x * blockDim.x + threadIdx.x) * 4;
    if (i + 4 <= E) {
        int4 s = *reinterpret_cast<const int4*>(src + i);
        int4 d = *reinterpret_cast<const int4*>(dst + i);
        int4 r = *reinterpret_cast<const int4*>(g_rank + i);
        int o0 = __ldg(g_off + d.x);
        int o1 = __ldg(g_off + d.y);
        int o2 = __ldg(g_off + d.z);
        int o3 = __ldg(g_off + d.w);
        g_esrc[o0 + r.x] = s.x;
        g_esrc[o1 + r.y] = s.y;
        g_esrc[o2 + r.z] = s.z;
        g_esrc[o3 + r.w] = s.w;
    } else {
        for (; i < E; i++) g_esrc[__ldg(g_off + dst[i]) + g_rank[i]] = src[i];
    }
}

// ---------------- tensor-core fp16 GEMM + fused elr epilogue ----------------
__device__ __forceinline__ uint32_t smem_u32(const void* p) {
    return (uint32_t)__cvta_generic_to_shared(p);
}
__device__ __forceinline__ void ldm_x4(uint32_t& r0, uint32_t& r1, uint32_t& r2, uint32_t& r3,
                                       uint32_t addr) {
    asm volatile("ldmatrix.sync.aligned.m8n8.x4.shared.b16 {%0,%1,%2,%3}, [%4];"
                 : "=r"(r0), "=r"(r1), "=r"(r2), "=r"(r3) : "r"(addr));
}
__device__ __forceinline__ void ldm_x4_t(uint32_t& r0, uint32_t& r1, uint32_t& r2, uint32_t& r3,
                                         uint32_t addr) {
    asm volatile("ldmatrix.sync.aligned.m8n8.x4.trans.shared.b16 {%0,%1,%2,%3}, [%4];"
                 : "=r"(r0), "=r"(r1), "=r"(r2), "=r"(r3) : "r"(addr));
}
__device__ __forceinline__ void mma16816(float& d0, float& d1, float& d2, float& d3,
                                         uint32_t a0, uint32_t a1, uint32_t a2, uint32_t a3,
                                         uint32_t b0, uint32_t b1) {
    asm volatile("mma.sync.aligned.m16n8k16.row.col.f32.f16.f16.f32 "
                 "{%0,%1,%2,%3}, {%4,%5,%6,%7}, {%8,%9}, {%0,%1,%2,%3};"
                 : "+f"(d0), "+f"(d1), "+f"(d2), "+f"(d3)
                 : "r"(a0), "r"(a1), "r"(a2), "r"(a3), "r"(b0), "r"(b1));
}

template<int BN, bool RELU_IN, typename AT>
__global__ __launch_bounds__(256)
void hgemm_fused(const AT* __restrict__ A, const float* __restrict__ B,
                 __half* __restrict__ Ch, float* __restrict__ gel, float* __restrict__ ger,
                 const float* __restrict__ attn_l, const float* __restrict__ attn_r,
                 int M, int Kd, int rowStart) {
    constexpr int BM = 128, BK = 32;
    constexpr int APAD = 8, BPAD = 8;
    constexpr int WN = BN / 2;
    constexpr int NT = WN / 8;
    __shared__ __align__(16) __half As[2][BM][BK + APAD];
    __shared__ __align__(16) __half Bs[2][BK][BN + BPAD];

    const int tid = threadIdx.x;
    const int wid = tid >> 5, lane = tid & 31;
    const int wm = wid & 3, wn = wid >> 2;
    const int rowBase = rowStart + blockIdx.x * BM;

    float acc[2][NT][4];
#pragma unroll
    for (int i = 0; i < 2; i++)
#pragma unroll
        for (int j = 0; j < NT; j++)
#pragma unroll
            for (int k = 0; k < 4; k++) acc[i][j][k] = 0.f;

    auto loadA = [&](int buf, int k0) {
#pragma unroll
        for (int it = 0; it < 2; it++) {
            int slot = tid + it * 256;
            int r = slot >> 2;
            int c8 = (slot & 3) * 8;
            int grow = rowBase + r;
            if constexpr (sizeof(AT) == 2) {
                uint4 u = make_uint4(0, 0, 0, 0);
                if (grow < M)
                    u = *reinterpret_cast<const uint4*>(A + (size_t)grow * Kd + k0 + c8);
                if (RELU_IN) {
                    half2 z = __float2half2_rn(0.f);
                    half2* hp = reinterpret_cast<half2*>(&u);
                    hp[0] = __hmax2(hp[0], z); hp[1] = __hmax2(hp[1], z);
                    hp[2] = __hmax2(hp[2], z); hp[3] = __hmax2(hp[3], z);
                }
                *reinterpret_cast<uint4*>(&As[buf][r][c8]) = u;
            } else {
                float4 v0 = make_float4(0.f, 0.f, 0.f, 0.f), v1 = v0;
                if (grow < M) {
                    const float* p = reinterpret_cast<const float*>(A) + (size_t)grow * Kd + k0 + c8;
                    v0 = *reinterpret_cast<const float4*>(p);
                    v1 = *reinterpret_cast<const float4*>(p + 4);
                }
                if (RELU_IN) {
                    v0.x = fmaxf(v0.x, 0.f); v0.y = fmaxf(v0.y, 0.f);
                    v0.z = fmaxf(v0.z, 0.f); v0.w = fmaxf(v0.w, 0.f);
                    v1.x = fmaxf(v1.x, 0.f); v1.y = fmaxf(v1.y, 0.f);
                    v1.z = fmaxf(v1.z, 0.f); v1.w = fmaxf(v1.w, 0.f);
                }
                half2 h0 = __floats2half2_rn(v0.x, v0.y);
                half2 h1 = __floats2half2_rn(v0.z, v0.w);
                half2 h2 = __floats2half2_rn(v1.x, v1.y);
                half2 h3 = __floats2half2_rn(v1.z, v1.w);
                uint4 u;
                u.x = *reinterpret_cast<unsigned*>(&h0);
                u.y = *reinterpret_cast<unsigned*>(&h1);
                u.z = *reinterpret_cast<unsigned*>(&h2);
                u.w = *reinterpret_cast<unsigned*>(&h3);
                *reinterpret_cast<uint4*>(&As[buf][r][c8]) = u;
            }
        }
    };
    auto loadB = [&](int buf, int k0) {
        constexpr int CG = BN / 8;
        constexpr int SLOTS = BK * CG;
        constexpr int ITERS = (SLOTS + 255) / 256;
#pragma unroll
        for (int it = 0; it < ITERS; it++) {
            int slot = tid + it * 256;
            if (SLOTS < 256 && slot >= SLOTS) break;
            int r = slot / CG;
            int c8 = (slot % CG) * 8;
            const float* p = B + (size_t)(k0 + r) * BN + c8;
            float4 v0 = *reinterpret_cast<const float4*>(p);
            float4 v1 = *reinterpret_cast<const float4*>(p + 4);
            half2 h0 = __floats2half2_rn(v0.x, v0.y);
            half2 h1 = __floats2half2_rn(v0.z, v0.w);
            half2 h2 = __floats2half2_rn(v1.x, v1.y);
            half2 h3 = __floats2half2_rn(v1.z, v1.w);
            uint4 u;
            u.x = *reinterpret_cast<unsigned*>(&h0);
            u.y = *reinterpret_cast<unsigned*>(&h1);
            u.z = *reinterpret_cast<unsigned*>(&h2);
            u.w = *reinterpret_cast<unsigned*>(&h3);
            *reinterpret_cast<uint4*>(&Bs[buf][r][c8]) = u;
        }
    };

    loadA(0, 0); loadB(0, 0);
    __syncthreads();
    const int KT = Kd / BK;
    for (int kt = 0; kt < KT; kt++) {
        int buf = kt & 1;
        if (kt + 1 < KT) { loadA(buf ^ 1, (kt + 1) * BK); loadB(buf ^ 1, (kt + 1) * BK); }
#pragma unroll
        for (int kc = 0; kc < 2; kc++) {
            int k16 = kc * 16;
            uint32_t af[2][4];
#pragma unroll
            for (int mt = 0; mt < 2; mt++) {
                uint32_t addr = smem_u32(&As[buf][wm * 32 + mt * 16 + (lane & 15)][k16 + (lane >> 4) * 8]);
                ldm_x4(af[mt][0], af[mt][1], af[mt][2], af[mt][3], addr);
            }
            uint32_t bf[NT][2];
#pragma unroll
            for (int nt2 = 0; nt2 < NT / 2; nt2++) {
                uint32_t addr = smem_u32(&Bs[buf][k16 + (lane & 15)][wn * WN + nt2 * 16 + (lane >> 4) * 8]);
                uint32_t r0, r1, r2, r3;
                ldm_x4_t(r0, r1, r2, r3, addr);
                bf[nt2 * 2][0] = r0; bf[nt2 * 2][1] = r1;
                bf[nt2 * 2 + 1][0] = r2; bf[nt2 * 2 + 1][1] = r3;
            }
#pragma unroll
            for (int mt = 0; mt < 2; mt++)
#pragma unroll
                for (int nt = 0; nt < NT; nt++)
                    mma16816(acc[mt][nt][0], acc[mt][nt][1], acc[mt][nt][2], acc[mt][nt][3],
                             af[mt][0], af[mt][1], af[mt][2], af[mt][3],
                             bf[nt][0], bf[nt][1]);
        }
        __syncthreads();
    }

    const int gid = lane >> 2, qid = lane & 3;

    // ---- fp16 mirror ----
#pragma unroll
    for (int mt = 0; mt < 2; mt++) {
        int r0 = rowBase + wm * 32 + mt * 16 + gid;
#pragma unroll
        for (int nt = 0; nt < NT; nt++) {
            int c = wn * WN + nt * 8 + qid * 2;
            if (r0 < M) {
                half2 hv = __floats2half2_rn(acc[mt][nt][0], acc[mt][nt][1]);
                *reinterpret_cast<unsigned*>(Ch + (size_t)r0 * BN + c) =
                    *reinterpret_cast<unsigned*>(&hv);
            }
            if (r0 + 8 < M) {
                half2 hv = __floats2half2_rn(acc[mt][nt][2], acc[mt][nt][3]);
                *reinterpret_cast<unsigned*>(Ch + (size_t)(r0 + 8) * BN + c) =
                    *reinterpret_cast<unsigned*>(&hv);
            }
        }
    }

    // ---- fused elr ----
    if constexpr (BN == 128) {
        float wl[16], wr[16];
#pragma unroll
        for (int nt = 0; nt < 8; nt++) {
            int c = wn * 64 + nt * 8 + qid * 2;
            wl[nt * 2 + 0] = __ldg(attn_l + c);
            wl[nt * 2 + 1] = __ldg(attn_l + c + 1);
            wr[nt * 2 + 0] = __ldg(attn_r + c);
            wr[nt * 2 + 1] = __ldg(attn_r + c + 1);
        }
#pragma unroll
        for (int mt = 0; mt < 2; mt++)
#pragma unroll
            for (int hf = 0; hf < 2; hf++) {
                int r = rowBase + wm * 32 + mt * 16 + hf * 8 + gid;
                float sel[4], ser[4];
#pragma unroll
                for (int hl = 0; hl < 4; hl++) {
                    int n0 = hl * 2, n1 = hl * 2 + 1;
                    sel[hl] = acc[mt][n0][hf * 2] * wl[n0 * 2] + acc[mt][n0][hf * 2 + 1] * wl[n0 * 2 + 1]
                            + acc[mt][n1][hf * 2] * wl[n1 * 2] + acc[mt][n1][hf * 2 + 1] * wl[n1 * 2 + 1];
                    ser[hl] = acc[mt][n0][hf * 2] * wr[n0 * 2] + acc[mt][n0][hf * 2 + 1] * wr[n0 * 2 + 1]
                            + acc[mt][n1][hf * 2] * wr[n1 * 2] + acc[mt][n1][hf * 2 + 1] * wr[n1 * 2 + 1];
                }
#pragma unroll
                for (int hl = 0; hl < 4; hl++) {
                    sel[hl] += __shfl_xor_sync(0xffffffffu, sel[hl], 1);
                    sel[hl] += __shfl_xor_sync(0xffffffffu, sel[hl], 2);
                    ser[hl] += __shfl_xor_sync(0xffffffffu, ser[hl], 1);
                    ser[hl] += __shfl_xor_sync(0xffffffffu, ser[hl], 2);
                }
                if (r < M) {
#pragma unroll
                    for (int hl = 0; hl < 4; hl++)
                        if (hl == qid) {
                            gel[(size_t)r * H1 + wn * 4 + hl] = sel[hl];
                            ger[(size_t)r * H1 + wn * 4 + hl] = ser[hl];
                        }
                }
            }
    } else {
        __shared__ float sEl[2][BM], sEr[2][BM];
        float wl[8], wr[8];
#pragma unroll
        for (int nt = 0; nt < 4; nt++) {
            int c = wn * 32 + nt * 8 + qid * 2;
            wl[nt * 2 + 0] = __ldg(attn_l + c);
            wl[nt * 2 + 1] = __ldg(attn_l + c + 1);
            wr[nt * 2 + 0] = __ldg(attn_r + c);
            wr[nt * 2 + 1] = __ldg(attn_r + c + 1);
        }
#pragma unroll
        for (int mt = 0; mt < 2; mt++)
#pragma unroll
            for (int hf = 0; hf < 2; hf++) {
                int lr = wm * 32 + mt * 16 + hf * 8 + gid;
                float sel = 0.f, ser = 0.f;
#pragma unroll
                for (int nt = 0; nt < 4; nt++) {
                    sel += acc[mt][nt][hf * 2] * wl[nt * 2] + acc[mt][nt][hf * 2 + 1] * wl[nt * 2 + 1];
                    ser += acc[mt][nt][hf * 2] * wr[nt * 2] + acc[mt][nt][hf * 2 + 1] * wr[nt * 2 + 1];
                }
                sel += __shfl_xor_sync(0xffffffffu, sel, 1);
                sel += __shfl_xor_sync(0xffffffffu, sel, 2);
                ser += __shfl_xor_sync(0xffffffffu, ser, 1);
                ser += __shfl_xor_sync(0xffffffffu, ser, 2);
                if (qid == 0) { sEl[wn][lr] = sel; sEr[wn][lr] = ser; }
            }
        __syncthreads();
        if (tid < BM) {
            int r = rowBase + tid;
            if (r < M) {
                gel[r] = sEl[0][tid] + sEl[1][tid];
                ger[r] = sEr[0][tid] + sEr[1][tid];
            }
        }
    }
}

// ---------------- layer1 agg: TWO warps per dst node, node-range variant ----------------
__global__ __launch_bounds__(256)
void agg1_kernel(const float* __restrict__ bias1, int nodeBase) {
    __shared__ float sAcc[4][32][5];
    int wid = threadIdx.x >> 5, lane = threadIdx.x & 31;
    int slot = wid >> 1, half = wid & 1;
    int w = nodeBase + blockIdx.x * 4 + slot;
    int h = lane >> 2;

    int beg = g_off[w], end = g_off[w + 1];
    int mid = (beg + end) >> 1;
    int b = half ? mid : beg;
    int e = half ? end : mid;
    float er_h = __ldg(g_er1 + (size_t)w * H1 + h);

    float acc0 = 0.f, acc1 = 0.f, acc2 = 0.f, acc3 = 0.f, ssum = 0.f;

    int i = b;
    for (; i + 4 <= e; i += 4) {
        int s0 = __ldg(g_esrc + i + 0);
        int s1 = __ldg(g_esrc + i + 1);
        int s2 = __ldg(g_esrc + i + 2);
        int s3 = __ldg(g_esrc + i + 3);
        float el0 = __ldg(g_el1 + (size_t)s0 * H1 + h);
        float el1 = __ldg(g_el1 + (size_t)s1 * H1 + h);
        float el2 = __ldg(g_el1 + (size_t)s2 * H1 + h);
        float el3 = __ldg(g_el1 + (size_t)s3 * H1 + h);
        uint2 u0 = *reinterpret_cast<const uint2*>(g_feat1h + (size_t)s0 * F_HID + lane * 4);
        uint2 u1 = *reinterpret_cast<const uint2*>(g_feat1h + (size_t)s1 * F_HID + lane * 4);
        uint2 u2 = *reinterpret_cast<const uint2*>(g_feat1h + (size_t)s2 * F_HID + lane * 4);
        uint2 u3 = *reinterpret_cast<const uint2*>(g_feat1h + (size_t)s3 * F_HID + lane * 4);
        float p0 = __expf(leaky(el0 + er_h));
        float p1 = __expf(leaky(el1 + er_h));
        float p2 = __expf(leaky(el2 + er_h));
        float p3 = __expf(leaky(el3 + er_h));
        {
            float2 a = __half22float2(*reinterpret_cast<half2*>(&u0.x));
            float2 c = __half22float2(*reinterpret_cast<half2*>(&u0.y));
            acc0 = fmaf(p0, a.x, acc0); acc1 = fmaf(p0, a.y, acc1);
            acc2 = fmaf(p0, c.x, acc2); acc3 = fmaf(p0, c.y, acc3);
        }
        {
            float2 a = __half22float2(*reinterpret_cast<half2*>(&u1.x));
            float2 c = __half22float2(*reinterpret_cast<half2*>(&u1.y));
            acc0 = fmaf(p1, a.x, acc0); acc1 = fmaf(p1, a.y, acc1);
            acc2 = fmaf(p1, c.x, acc2); acc3 = fmaf(p1, c.y, acc3);
        }
        {
            float2 a = __half22float2(*reinterpret_cast<half2*>(&u2.x));
            float2 c = __half22float2(*reinterpret_cast<half2*>(&u2.y));
            acc0 = fmaf(p2, a.x, acc0); acc1 = fmaf(p2, a.y, acc1);
            acc2 = fmaf(p2, c.x, acc2); acc3 = fmaf(p2, c.y, acc3);
        }
        {
            float2 a = __half22float2(*reinterpret_cast<half2*>(&u3.x));
            float2 c = __half22float2(*reinterpret_cast<half2*>(&u3.y));
            acc0 = fmaf(p3, a.x, acc0); acc1 = fmaf(p3, a.y, acc1);
            acc2 = fmaf(p3, c.x, acc2); acc3 = fmaf(p3, c.y, acc3);
        }
        ssum += (p0 + p1) + (p2 + p3);
    }
    for (; i < e; i++) {
        int s = __ldg(g_esrc + i);
        float el = __ldg(g_el1 + (size_t)s * H1 + h);
        uint2 u = *reinterpret_cast<const uint2*>(g_feat1h + (size_t)s * F_HID + lane * 4);
        float p = __expf(leaky(el + er_h));
        float2 a = __half22float2(*reinterpret_cast<half2*>(&u.x));
        float2 c = __half22float2(*reinterpret_cast<half2*>(&u.y));
        acc0 = fmaf(p, a.x, acc0); acc1 = fmaf(p, a.y, acc1);
        acc2 = fmaf(p, c.x, acc2); acc3 = fmaf(p, c.y, acc3);
        ssum += p;
    }

    if (half) {
        sAcc[slot][lane][0] = acc0;
        sAcc[slot][lane][1] = acc1;
        sAcc[slot][lane][2] = acc2;
        sAcc[slot][lane][3] = acc3;
        sAcc[slot][lane][4] = ssum;
    }
    __syncthreads();
    if (!half) {
        acc0 += sAcc[slot][lane][0];
        acc1 += sAcc[slot][lane][1];
        acc2 += sAcc[slot][lane][2];
        acc3 += sAcc[slot][lane][3];
        ssum += sAcc[slot][lane][4];
        float inv = 1.f / fmaxf(ssum, 1e-9f);
        float4 bb = *reinterpret_cast<const float4*>(bias1 + lane * 4);
        half2 o0 = __floats2half2_rn(acc0 * inv + bb.x, acc1 * inv + bb.y);
        half2 o1 = __floats2half2_rn(acc2 * inv + bb.z, acc3 * inv + bb.w);
        uint2 ou;
        ou.x = *reinterpret_cast<unsigned*>(&o0);
        ou.y = *reinterpret_cast<unsigned*>(&o1);
        *reinterpret_cast<uint2*>(g_h1h + (size_t)w * F_HID + lane * 4) = ou;
    }
}

// ---------------- layer2 agg: TWO warps per dst node ----------------
__global__ __launch_bounds__(256)
void agg2_kernel(const float* __restrict__ bias2, float* __restrict__ out) {
    __shared__ float sAcc[4][32][3];
    int wid = threadIdx.x >> 5, lane = threadIdx.x & 31;
    int slot = wid >> 1, half = wid & 1;
    int w = blockIdx.x * 4 + slot;

    int beg = g_off[w], end = g_off[w + 1];
    int mid = (beg + end) >> 1;
    int b = half ? mid : beg;
    int e = half ? end : mid;
    float er = __ldg(g_er2 + w);

    float acc0 = 0.f, acc1 = 0.f, ssum = 0.f;

    int i = b;
    for (; i + 4 <= e; i += 4) {
        int s0 = __ldg(g_esrc + i + 0);
        int s1 = __ldg(g_esrc + i + 1);
        int s2 = __ldg(g_esrc + i + 2);
        int s3 = __ldg(g_esrc + i + 3);
        float el0 = __ldg(g_el2 + s0);
        float el1 = __ldg(g_el2 + s1);
        float el2 = __ldg(g_el2 + s2);
        float el3 = __ldg(g_el2 + s3);
        unsigned u0 = *reinterpret_cast<const unsigned*>(g_feat2h + (size_t)s0 * F_OUT + lane * 2);
        unsigned u1 = *reinterpret_cast<const unsigned*>(g_feat2h + (size_t)s1 * F_OUT + lane * 2);
        unsigned u2 = *reinterpret_cast<const unsigned*>(g_feat2h + (size_t)s2 * F_OUT + lane * 2);
        unsigned u3 = *reinterpret_cast<const unsigned*>(g_feat2h + (size_t)s3 * F_OUT + lane * 2);
        float p0 = __expf(leaky(el0 + er));
        float p1 = __expf(leaky(el1 + er));
        float p2 = __expf(leaky(el2 + er));
        float p3 = __expf(leaky(el3 + er));
        float2 f0 = __half22float2(*reinterpret_cast<half2*>(&u0));
        float2 f1 = __half22float2(*reinterpret_cast<half2*>(&u1));
        float2 f2 = __half22float2(*reinterpret_cast<half2*>(&u2));
        float2 f3 = __half22float2(*reinterpret_cast<half2*>(&u3));
        acc0 = fmaf(p0, f0.x, acc0); acc1 = fmaf(p0, f0.y, acc1);
        acc0 = fmaf(p1, f1.x, acc0); acc1 = fmaf(p1, f1.y, acc1);
        acc0 = fmaf(p2, f2.x, acc0); acc1 = fmaf(p2, f2.y, acc1);
        acc0 = fmaf(p3, f3.x, acc0); acc1 = fmaf(p3, f3.y, acc1);
        ssum += (p0 + p1) + (p2 + p3);
    }
    for (; i < e; i++) {
        int s = __ldg(g_esrc + i);
        float el = __ldg(g_el2 + s);
        unsigned u = *reinterpret_cast<const unsigned*>(g_feat2h + (size_t)s * F_OUT + lane * 2);
        float p = __expf(leaky(el + er));
        float2 f = __half22float2(*reinterpret_cast<half2*>(&u));
        acc0 = fmaf(p, f.x, acc0); acc1 = fmaf(p, f.y, acc1);
        ssum += p;
    }

    if (half) {
        sAcc[slot][lane][0] = acc0;
        sAcc[slot][lane][1] = acc1;
        sAcc[slot][lane][2] = ssum;
    }
    __syncthreads();
    if (!half) {
        acc0 += sAcc[slot][lane][0];
        acc1 += sAcc[slot][lane][1];
        ssum += sAcc[slot][lane][2];
        float inv = 1.f / fmaxf(ssum, 1e-9f);
        float2 bb = *reinterpret_cast<const float2*>(bias2 + lane * 2);
        float2 o = make_float2(acc0 * inv + bb.x, acc1 * inv + bb.y);
        *reinterpret_cast<float2*>(out + (size_t)w * F_OUT + lane * 2) = o;
    }
}

// ---------------- launch ----------------
extern "C" void kernel_launch(void* const* d_in, const int* in_sizes, int n_in,
                              void* d_out, int out_size) {
    const float* x   = (const float*)d_in[0];
    const int*   src = (const int*)  d_in[1];
    const int*   dst = (const int*)  d_in[2];
    const float* W1  = (const float*)d_in[3];
    const float* al1 = (const float*)d_in[4];
    const float* ar1 = (const float*)d_in[5];
    const float* b1  = (const float*)d_in[6];
    const float* W2  = (const float*)d_in[7];
    const float* al2 = (const float*)d_in[8];
    const float* ar2 = (const float*)d_in[9];
    const float* b2  = (const float*)d_in[10];
    float* out = (float*)d_out;
    const int E = in_sizes[1];
    const int M = NN;

    __half *feat1h, *h1h, *feat2h;
    float *el1, *er1, *el2, *er2;
    cudaGetSymbolAddress((void**)&feat1h, g_feat1h);
    cudaGetSymbolAddress((void**)&h1h,    g_h1h);
    cudaGetSymbolAddress((void**)&feat2h, g_feat2h);
    cudaGetSymbolAddress((void**)&el1, g_el1);
    cudaGetSymbolAddress((void**)&er1, g_er1);
    cudaGetSymbolAddress((void**)&el2, g_el2);
    cudaGetSymbolAddress((void**)&er2, g_er2);

    static cudaStream_t s_side = nullptr;
    static cudaEvent_t  s_fork = nullptr, s_join = nullptr, s_evA = nullptr, s_evG = nullptr;
    if (!s_side) {
        cudaStreamCreateWithFlags(&s_side, cudaStreamNonBlocking);
        cudaEventCreateWithFlags(&s_fork, cudaEventDisableTiming);
        cudaEventCreateWithFlags(&s_join, cudaEventDisableTiming);
        cudaEventCreateWithFlags(&s_evA,  cudaEventDisableTiming);
        cudaEventCreateWithFlags(&s_evG,  cudaEventDisableTiming);
    }

    // fork side stream
    cudaEventRecord(s_fork, 0);
    cudaStreamWaitEvent(s_side, s_fork, 0);

    // main: layer-1 GEMM
    hgemm_fused<F_HID, false, float><<<(M + 127) / 128, 256>>>(
        x, W1, feat1h, el1, er1, al1, ar1, M, F_IN, 0);

    // side: CSR build
    hist_kernel<<<(E / 4 + 255) / 256, 256, 0, s_side>>>(dst, E);
    scan_kernel<<<1, 1024, 0, s_side>>>(E);
    place_kernel<<<(E / 4 + 255) / 256, 256, 0, s_side>>>(src, dst, E);
    cudaEventRecord(s_join, s_side);

    // agg1 first half -> enables gemm2a
    cudaStreamWaitEvent(0, s_join, 0);
    agg1_kernel<<<NSPLIT / 4, 256>>>(b1, 0);
    cudaEventRecord(s_evA, 0);

    // side: gemm2 on rows [0, NSPLIT) concurrent with agg1 second half
    cudaStreamWaitEvent(s_side, s_evA, 0);
    hgemm_fused<F_OUT, true, __half><<<NSPLIT / 128, 256, 0, s_side>>>(
        h1h, W2, feat2h, el2, er2, al2, ar2, M, F_HID, 0);
    cudaEventRecord(s_evG, s_side);

    // main: agg1 second half, then gemm2 on remaining rows
    agg1_kernel<<<(NN - NSPLIT) / 4, 256>>>(b1, NSPLIT);
    hgemm_fused<F_OUT, true, __half><<<(M - NSPLIT + 127) / 128, 256>>>(
        h1h, W2, feat2h, el2, er2, al2, ar2, M, F_HID, NSPLIT);

    // agg2 needs both gemm2 halves
    cudaStreamWaitEvent(0, s_evG, 0);
    agg2_kernel<<<NN / 4, 256>>>(b2, out);
}